// round 12
// baseline (speedup 1.0000x reference)
#include <cuda_runtime.h>
#include <math.h>

#define HWSZ   9216
#define GH     96
#define GW     96
#define NPAIR  16                  // 8 samples x 2 directions
#define BANDS  4
#define RPB    (GH / BANDS)        // 24 rows per band
#define BPX    (RPB * GW)          // 2304 pixels per band
#define NT     768
#define PPT    (BPX / NT)          // 3 pixels per thread, exact
#define NBLK   (NPAIR * BANDS)     // 64 blocks

// global scratch (per-pair 1D row distance, u8) + control state
__device__ unsigned char g_rd[NPAIR][HWSZ];
__device__ int      g_pairmax[NPAIR] = {-1,-1,-1,-1,-1,-1,-1,-1,
                                        -1,-1,-1,-1,-1,-1,-1,-1};
__device__ int      g_tcnt[NPAIR];        // zero-init
__device__ unsigned g_c1[NPAIR];          // per-pair band barrier, zero-init
__device__ unsigned g_cd[NPAIR];          // per-pair completion counter, zero-init
__device__ unsigned g_c2 = 0;             // pair-level completion counter (16 arrivals)

// pair = 2*sample + dir.
//   dir 0: src = A & ~B, tgt = B   (distA)
//   dir 1: src = ~A & B, tgt = A   (distB)
__global__ __launch_bounds__(NT) void hausdorff_kernel(
    const float* __restrict__ predict,
    const float* __restrict__ target,
    float* __restrict__ out)
{
    const int pair = blockIdx.x / BANDS;
    const int band = blockIdx.x - pair * BANDS;
    const int dir  = pair & 1;
    const int tid  = threadIdx.x;
    const int base = band * BPX;           // absolute pixel base of this band

    // padded row-bit layout: 8 words/row = [0,0, w0,w1,w2, 0,0,0]; row base = i*8+2
    __shared__ unsigned       s_tgtpad[RPB * 8];    // 192 words
    __shared__ unsigned       s_srcbits[BPX / 32];  // 72 words
    __shared__ unsigned char  s_rd[HWSZ];           // full-tile 1D row distance (9 KB)
    __shared__ int            s_warpmax[NT / 32];

    const float* pa = predict + (pair >> 1) * HWSZ;
    const float* pb = target  + (pair >> 1) * HWSZ;

    // ---- prefetch input scalars first: start the LDG wave before any setup ----
    float va[PPT], vb[PPT];
    #pragma unroll
    for (int k = 0; k < PPT; k++) {
        const int p = base + tid + k * NT;
        va[k] = pa[p];
        vb[k] = pb[p];
    }

    // zero the 5 pad words per row (disjoint from ballot-written data words)
    if (tid < RPB * 5) {
        int r = tid / 5, pi = tid % 5;
        s_tgtpad[r * 8 + ((pi < 2) ? pi : pi + 3)] = 0u;
    }

    // ---- Phase 1: masks for this band (rintf(x)>0.5 <=> x>0.5, half-even) ----
    int tcount = 0;
    #pragma unroll
    for (int k = 0; k < PPT; k++) {
        const int lp = tid + k * NT;       // 0..2303, lane0 word-aligned
        bool a = va[k] > 0.5f;
        bool b = vb[k] > 0.5f;
        bool t = dir ? a : b;
        bool s = dir ? ((!a) && b) : (a && (!b));
        unsigned tb = __ballot_sync(0xffffffffu, t);
        unsigned sb = __ballot_sync(0xffffffffu, s);
        if ((tid & 31) == 0) {
            const int ww = lp >> 5;        // 0..71
            const int li = ww / 3, wi = ww - li * 3;
            s_tgtpad[li * 8 + 2 + wi] = tb;
            s_srcbits[ww] = sb;
            tcount += __popc(tb);
        }
    }
    if ((tid & 31) == 0 && tcount) atomicAdd(&g_tcnt[pair], tcount);
    __syncthreads();

    // ---- Phase 2: 1D row distance via padded-row indexed loads + 64-bit scans ----
    #pragma unroll
    for (int k = 0; k < PPT; k++) {
        const int lp = tid + k * NT;
        const int li = lp / GW;
        const int j  = lp - li * GW;
        const int w  = j >> 5, off = j & 31;
        const unsigned* bw = s_tgtpad + li * 8 + 2 + w;   // padded: bw[-2..2] valid
        unsigned d2v = bw[-2], d1v = bw[-1], m = bw[0], u1v = bw[1], u2v = bw[2];
        unsigned hi = 0xffffffffu << off;
        unsigned lo = (2u << off) - 1u;     // off=31 wraps to ~0

        unsigned long long upair = (unsigned long long)(m & hi)
                                 | ((unsigned long long)u1v << 32);
        unsigned long long dpair = (unsigned long long)d1v
                                 | ((unsigned long long)(m & lo) << 32);

        int up = upair ? (w * 32 + __ffsll(upair) - 1 - j)
               : (u2v  ? (w * 32 + 64 + __ffs(u2v) - 1 - j) : 1000);
        int dn = dpair ? (j - (w * 32 - 32 + 63 - __clzll(dpair)))
               : (d2v  ? (j - (w * 32 - 64 + 31 - __clz(d2v))) : 1000);
        int d = min(min(up, dn), 255);              // empty-row sentinel
        g_rd[pair][base + lp] = (unsigned char)d;   // u8 exchange (d <= 95 or 255)
    }

    // ---- per-pair barrier: all 4 bands' rd visible ----
    __syncthreads();
    if (tid == 0) {
        __threadfence();                            // release rd writes
        atomicAdd(&g_c1[pair], 1u);
        volatile unsigned* c = &g_c1[pair];
        while (*c < BANDS) { }
        __threadfence();                            // acquire
    }
    __syncthreads();

    // ---- Phase 3a: pull full 9KB rd tile L2 -> smem, one LDG.128 per thread ----
    if (tid < HWSZ / 16) {                          // 576 uint4 loads, single wave
        const uint4* gsrc = (const uint4*)&g_rd[pair][0];
        ((uint4*)s_rd)[tid] = __ldcg(gsrc + tid);
    }
    __syncthreads();

    // ---- Phase 3b: exact early-exit ring search (columns), src px only ----
    int maxd2 = -1;
    #pragma unroll
    for (int k = 0; k < PPT; k++) {
        const int lp = tid + k * NT;
        if ((s_srcbits[lp >> 5] >> (lp & 31)) & 1u) {
            const int p = base + lp;
            const int i = p / GW;                   // absolute row
            int d0 = (int)s_rd[p];
            int best = d0 * d0;                     // sentinel 255^2 > any true d2
            for (int r = 1; r < GH && r * r < best; r++) {
                int rr = r * r;
                if (i >= r) {
                    int du = (int)s_rd[p - r * GW];
                    best = min(best, rr + du * du);
                }
                if (i + r < GH) {
                    int dd = (int)s_rd[p + r * GW];
                    best = min(best, rr + dd * dd);
                }
            }
            maxd2 = max(maxd2, best);
        }
    }

    // ---- Phase 4: block reduce -> atomicMax -> hierarchical completion ----
    #pragma unroll
    for (int off = 16; off > 0; off >>= 1)
        maxd2 = max(maxd2, __shfl_xor_sync(0xffffffffu, maxd2, off));
    if ((tid & 31) == 0) s_warpmax[tid >> 5] = maxd2;
    __syncthreads();

    if (tid == 0) {
        int m = -1;
        #pragma unroll
        for (int w = 0; w < NT / 32; w++) m = max(m, s_warpmax[w]);
        if (m >= 0) atomicMax(&g_pairmax[pair], m);

        __threadfence();                            // release max/tcnt writes
        // level 1: per-pair counter (16 independent addresses, parallel)
        unsigned d1 = atomicAdd(&g_cd[pair], 1u);
        if (d1 == BANDS - 1) {
            // level 2: only 16 pair-last blocks touch the global counter
            unsigned d2 = atomicAdd(&g_c2, 1u);
            if (d2 == NPAIR - 1) {                  // global-last block finalizes
                __threadfence();                    // acquire all blocks' writes
                int pm[NPAIR], tc[NPAIR];
                #pragma unroll
                for (int q = 0; q < NPAIR; q++) {   // batched independent L2 loads
                    pm[q] = __ldcg(&g_pairmax[q]);
                    tc[q] = __ldcg(&g_tcnt[q]);
                }
                float s = 0.0f;
                #pragma unroll
                for (int q = 0; q < 8; q++) {
                    float v0 = (pm[2*q]   < 0) ? 0.0f : ((tc[2*q]   == 0) ? 1e9f : sqrtf((float)pm[2*q])   * (1.0f/96.0f));
                    float v1 = (pm[2*q+1] < 0) ? 0.0f : ((tc[2*q+1] == 0) ? 1e9f : sqrtf((float)pm[2*q+1]) * (1.0f/96.0f));
                    s += fmaxf(v0, v1);
                }
                out[0] = s * 0.125f;
                // reset all control state for the next graph replay
                #pragma unroll
                for (int q = 0; q < NPAIR; q++) {
                    g_pairmax[q] = -1;
                    g_tcnt[q]    = 0;
                    g_c1[q]      = 0;
                    g_cd[q]      = 0;
                }
                g_c2 = 0;
                __threadfence();
            }
        }
    }
}

extern "C" void kernel_launch(void* const* d_in, const int* in_sizes, int n_in,
                              void* d_out, int out_size)
{
    const float* predict = (const float*)d_in[0];
    const float* target  = (const float*)d_in[1];
    hausdorff_kernel<<<NBLK, NT>>>(predict, target, (float*)d_out);
}

// round 13
// speedup vs baseline: 1.1831x; 1.1831x over previous
#include <cuda_runtime.h>
#include <math.h>

#define HWSZ   9216
#define GH     96
#define GW     96
#define NPAIR  16                  // 8 samples x 2 directions
#define BANDS  8
#define RPB    (GH / BANDS)        // 12 rows per band
#define BPX    (RPB * GW)          // 1152 pixels per band
#define NT     384
#define PPT    (BPX / NT)          // 3 pixels per thread, exact
#define NBLK   (NPAIR * BANDS)     // 128 blocks

// global scratch (per-pair 1D row distance, u8) + control state
__device__ unsigned char g_rd[NPAIR][HWSZ];
__device__ int      g_pairmax[NPAIR] = {-1,-1,-1,-1,-1,-1,-1,-1,
                                        -1,-1,-1,-1,-1,-1,-1,-1};
__device__ int      g_tcnt[NPAIR];        // zero-init
__device__ unsigned g_c1[NPAIR];          // per-pair band barrier, zero-init
__device__ unsigned g_c2 = 0;             // flat global completion counter (128 arrivals)

// pair = 2*sample + dir.
//   dir 0: src = A & ~B, tgt = B   (distA)
//   dir 1: src = ~A & B, tgt = A   (distB)
__global__ __launch_bounds__(NT) void hausdorff_kernel(
    const float* __restrict__ predict,
    const float* __restrict__ target,
    float* __restrict__ out)
{
    const int pair = blockIdx.x >> 3;
    const int band = blockIdx.x & 7;
    const int dir  = pair & 1;
    const int tid  = threadIdx.x;
    const int base = band * BPX;           // absolute pixel base of this band

    // padded row-bit layout: 8 words/row = [0,0, w0,w1,w2, 0,0,0]; row base = i*8+2
    __shared__ unsigned       s_tgtpad[RPB * 8];    // 96 words
    __shared__ unsigned       s_srcbits[BPX / 32];  // 36 words
    __shared__ unsigned char  s_rd[HWSZ];           // full-tile 1D row distance (9 KB)
    __shared__ int            s_warpmax[NT / 32];
    __shared__ int            s_wcnt[NT / 32];

    const float* pa = predict + (pair >> 1) * HWSZ;
    const float* pb = target  + (pair >> 1) * HWSZ;

    // ---- prefetch input scalars first: start the LDG wave before any setup ----
    float va[PPT], vb[PPT];
    #pragma unroll
    for (int k = 0; k < PPT; k++) {
        const int p = base + tid + k * NT;
        va[k] = pa[p];
        vb[k] = pb[p];
    }

    // zero the 5 pad words per row (disjoint from ballot-written data words)
    if (tid < RPB * 5) {
        int r = tid / 5, pi = tid % 5;
        s_tgtpad[r * 8 + ((pi < 2) ? pi : pi + 3)] = 0u;
    }

    // ---- Phase 1: masks for this band (rintf(x)>0.5 <=> x>0.5, half-even) ----
    int tcount = 0;
    #pragma unroll
    for (int k = 0; k < PPT; k++) {
        const int lp = tid + k * NT;       // 0..1151, lane0 word-aligned
        bool a = va[k] > 0.5f;
        bool b = vb[k] > 0.5f;
        bool t = dir ? a : b;
        bool s = dir ? ((!a) && b) : (a && (!b));
        unsigned tb = __ballot_sync(0xffffffffu, t);
        unsigned sb = __ballot_sync(0xffffffffu, s);
        if ((tid & 31) == 0) {
            const int ww = lp >> 5;        // 0..35
            const int li = ww / 3, wi = ww - li * 3;
            s_tgtpad[li * 8 + 2 + wi] = tb;
            s_srcbits[ww] = sb;
            tcount += __popc(tb);
        }
    }
    if ((tid & 31) == 0) s_wcnt[tid >> 5] = tcount;   // smem, not global atomics
    __syncthreads();

    // single global atomic per block for the tgt count (overlaps phase 2 in other warps)
    if (tid == 0) {
        int tc = 0;
        #pragma unroll
        for (int w = 0; w < NT / 32; w++) tc += s_wcnt[w];
        if (tc) atomicAdd(&g_tcnt[pair], tc);
    }

    // ---- Phase 2: 1D row distance via padded-row indexed loads + 64-bit scans ----
    #pragma unroll
    for (int k = 0; k < PPT; k++) {
        const int lp = tid + k * NT;
        const int li = lp / GW;
        const int j  = lp - li * GW;
        const int w  = j >> 5, off = j & 31;
        const unsigned* bw = s_tgtpad + li * 8 + 2 + w;   // padded: bw[-2..2] valid
        unsigned d2v = bw[-2], d1v = bw[-1], m = bw[0], u1v = bw[1], u2v = bw[2];
        unsigned hi = 0xffffffffu << off;
        unsigned lo = (2u << off) - 1u;     // off=31 wraps to ~0

        unsigned long long upair = (unsigned long long)(m & hi)
                                 | ((unsigned long long)u1v << 32);
        unsigned long long dpair = (unsigned long long)d1v
                                 | ((unsigned long long)(m & lo) << 32);

        int up = upair ? (w * 32 + __ffsll(upair) - 1 - j)
               : (u2v  ? (w * 32 + 64 + __ffs(u2v) - 1 - j) : 1000);
        int dn = dpair ? (j - (w * 32 - 32 + 63 - __clzll(dpair)))
               : (d2v  ? (j - (w * 32 - 64 + 31 - __clz(d2v))) : 1000);
        int d = min(min(up, dn), 255);              // empty-row sentinel
        g_rd[pair][base + lp] = (unsigned char)d;   // u8 exchange (d <= 95 or 255)
    }

    // ---- per-pair barrier: all 8 bands' rd visible ----
    __syncthreads();
    if (tid == 0) {
        __threadfence();                            // release rd writes
        unsigned arrived = atomicAdd(&g_c1[pair], 1u) + 1u;
        if (arrived < BANDS) {                      // last arriver skips the poll
            volatile unsigned* c = &g_c1[pair];
            while (*c < BANDS) { }
        }
        __threadfence();                            // acquire
    }
    __syncthreads();

    // ---- Phase 3a: pull full 9KB rd tile L2 -> smem, 64-bit loads ----
    {
        const uint2* gsrc = (const uint2*)&g_rd[pair][0];   // 1152 uint2
        uint2* sdst = (uint2*)s_rd;
        #pragma unroll
        for (int k = 0; k < 3; k++)
            sdst[tid + k * NT] = __ldcg(gsrc + tid + k * NT);
    }
    __syncthreads();

    // ---- Phase 3b: exact early-exit ring search (columns), src px only ----
    int maxd2 = -1;
    #pragma unroll
    for (int k = 0; k < PPT; k++) {
        const int lp = tid + k * NT;
        if ((s_srcbits[lp >> 5] >> (lp & 31)) & 1u) {
            const int p = base + lp;
            const int i = p / GW;                   // absolute row
            int d0 = (int)s_rd[p];
            int best = d0 * d0;                     // sentinel 255^2 > any true d2
            for (int r = 1; r < GH && r * r < best; r++) {
                int rr = r * r;
                if (i >= r) {
                    int du = (int)s_rd[p - r * GW];
                    best = min(best, rr + du * du);
                }
                if (i + r < GH) {
                    int dd = (int)s_rd[p + r * GW];
                    best = min(best, rr + dd * dd);
                }
            }
            maxd2 = max(maxd2, best);
        }
    }

    // ---- Phase 4: block reduce -> per-pair atomicMax -> last-block finalize ----
    #pragma unroll
    for (int off = 16; off > 0; off >>= 1)
        maxd2 = max(maxd2, __shfl_xor_sync(0xffffffffu, maxd2, off));
    if ((tid & 31) == 0) s_warpmax[tid >> 5] = maxd2;
    __syncthreads();

    if (tid == 0) {
        int m = -1;
        #pragma unroll
        for (int w = 0; w < NT / 32; w++) m = max(m, s_warpmax[w]);
        if (m >= 0) atomicMax(&g_pairmax[pair], m);

        __threadfence();                            // release max/tcnt writes
        unsigned done = atomicAdd(&g_c2, 1u);
        if (done == NBLK - 1) {                     // last block finalizes
            __threadfence();                        // acquire all blocks' writes
            // batched, independent L2 loads (MLP-covered)
            int pm[NPAIR], tc[NPAIR];
            #pragma unroll
            for (int q = 0; q < NPAIR; q++) {
                pm[q] = __ldcg(&g_pairmax[q]);
                tc[q] = __ldcg(&g_tcnt[q]);
            }
            float s = 0.0f;
            #pragma unroll
            for (int q = 0; q < 8; q++) {
                float v0 = (pm[2*q]   < 0) ? 0.0f : ((tc[2*q]   == 0) ? 1e9f : sqrtf((float)pm[2*q])   * (1.0f/96.0f));
                float v1 = (pm[2*q+1] < 0) ? 0.0f : ((tc[2*q+1] == 0) ? 1e9f : sqrtf((float)pm[2*q+1]) * (1.0f/96.0f));
                s += fmaxf(v0, v1);
            }
            out[0] = s * 0.125f;
            // reset all control state for the next graph replay
            #pragma unroll
            for (int q = 0; q < NPAIR; q++) {
                g_pairmax[q] = -1;
                g_tcnt[q]    = 0;
                g_c1[q]      = 0;
            }
            g_c2 = 0;
            __threadfence();
        }
    }
}

extern "C" void kernel_launch(void* const* d_in, const int* in_sizes, int n_in,
                              void* d_out, int out_size)
{
    const float* predict = (const float*)d_in[0];
    const float* target  = (const float*)d_in[1];
    hausdorff_kernel<<<NBLK, NT>>>(predict, target, (float*)d_out);
}

// round 16
// speedup vs baseline: 1.2149x; 1.0269x over previous
#include <cuda_runtime.h>
#include <math.h>

#define HWSZ   9216
#define GH     96
#define GW     96
#define NPAIR  16                  // 8 samples x 2 directions
#define BANDS  8
#define RPB    (GH / BANDS)        // 12 rows per band
#define BPX    (RPB * GW)          // 1152 pixels per band
#define NT     384
#define PPT    (BPX / NT)          // 3 pixels per thread, exact
#define NBLK   (NPAIR * BANDS)     // 128 blocks
#define PADR   GH                  // sentinel rows above/below the rd tile

// global scratch (per-pair 1D row distance, u8) + control state
__device__ unsigned char g_rd[NPAIR][HWSZ];
__device__ int      g_pairmax[NPAIR] = {-1,-1,-1,-1,-1,-1,-1,-1,
                                        -1,-1,-1,-1,-1,-1,-1,-1};
__device__ int      g_tcnt[NPAIR];        // zero-init
__device__ unsigned g_c1[NPAIR];          // per-pair band barrier, zero-init
__device__ unsigned g_c2 = 0;             // flat global completion counter (128 arrivals)

// pair = 2*sample + dir.
//   dir 0: src = A & ~B, tgt = B   (distA)
//   dir 1: src = ~A & B, tgt = A   (distB)
__global__ __launch_bounds__(NT) void hausdorff_kernel(
    const float* __restrict__ predict,
    const float* __restrict__ target,
    float* __restrict__ out)
{
    const int pair = blockIdx.x >> 3;
    const int band = blockIdx.x & 7;
    const int dir  = pair & 1;
    const int tid  = threadIdx.x;
    const int base = band * BPX;           // absolute pixel base of this band

    // padded row-bit layout: 8 words/row = [0,0, w0,w1,w2, 0,0,0]; row base = i*8+2
    __shared__ unsigned       s_tgtpad[RPB * 8];    // 96 words
    __shared__ unsigned       s_srcbits[BPX / 32];  // 36 words
    // rd tile padded with PADR sentinel rows above and below: ring loop is branch-free
    __shared__ unsigned char  s_rdbuf[(GH + 2 * PADR) * GW];   // 27648 B
    __shared__ int            s_warpmax[NT / 32];
    __shared__ int            s_wcnt[NT / 32];

    unsigned char* const s_rd = s_rdbuf + PADR * GW;  // s_rd[0..HWSZ) = real tile

    const float* pa = predict + (pair >> 1) * HWSZ;
    const float* pb = target  + (pair >> 1) * HWSZ;

    // ---- prefetch input scalars first: start the LDG wave before any setup ----
    float va[PPT], vb[PPT];
    #pragma unroll
    for (int k = 0; k < PPT; k++) {
        const int p = base + tid + k * NT;
        va[k] = pa[p];
        vb[k] = pb[p];
    }

    // fill sentinel pad rows (255 => d2 contribution >= rr + 65025, never the min)
    {
        uint4 s255 = make_uint4(0xffffffffu, 0xffffffffu, 0xffffffffu, 0xffffffffu);
        uint4* lo = (uint4*)s_rdbuf;                        // PADR*GW/16 = 576 uint4
        uint4* hi = (uint4*)(s_rdbuf + (PADR + GH) * GW);
        #pragma unroll
        for (int k = 0; k < (PADR * GW / 16) / NT + 1; k++) {
            const int q = tid + k * NT;
            if (q < PADR * GW / 16) { lo[q] = s255; hi[q] = s255; }
        }
    }

    // zero the 5 pad words per row (disjoint from ballot-written data words)
    if (tid < RPB * 5) {
        int r = tid / 5, pi = tid % 5;
        s_tgtpad[r * 8 + ((pi < 2) ? pi : pi + 3)] = 0u;
    }

    // ---- Phase 1: masks for this band (rintf(x)>0.5 <=> x>0.5, half-even) ----
    int tcount = 0;
    #pragma unroll
    for (int k = 0; k < PPT; k++) {
        const int lp = tid + k * NT;       // 0..1151, lane0 word-aligned
        bool a = va[k] > 0.5f;
        bool b = vb[k] > 0.5f;
        bool t = dir ? a : b;
        bool s = dir ? ((!a) && b) : (a && (!b));
        unsigned tb = __ballot_sync(0xffffffffu, t);
        unsigned sb = __ballot_sync(0xffffffffu, s);
        if ((tid & 31) == 0) {
            const int ww = lp >> 5;        // 0..35
            const int li = ww / 3, wi = ww - li * 3;
            s_tgtpad[li * 8 + 2 + wi] = tb;
            s_srcbits[ww] = sb;
            tcount += __popc(tb);
        }
    }
    if ((tid & 31) == 0) s_wcnt[tid >> 5] = tcount;   // smem, not global atomics
    __syncthreads();

    // single global atomic per block for the tgt count (overlaps phase 2 in other warps)
    if (tid == 0) {
        int tc = 0;
        #pragma unroll
        for (int w = 0; w < NT / 32; w++) tc += s_wcnt[w];
        if (tc) atomicAdd(&g_tcnt[pair], tc);
    }

    // ---- Phase 2: 1D row distance via padded-row indexed loads + 64-bit scans ----
    #pragma unroll
    for (int k = 0; k < PPT; k++) {
        const int lp = tid + k * NT;
        const int li = lp / GW;
        const int j  = lp - li * GW;
        const int w  = j >> 5, off = j & 31;
        const unsigned* bw = s_tgtpad + li * 8 + 2 + w;   // padded: bw[-2..2] valid
        unsigned d2v = bw[-2], d1v = bw[-1], m = bw[0], u1v = bw[1], u2v = bw[2];
        unsigned hi = 0xffffffffu << off;
        unsigned lo = (2u << off) - 1u;     // off=31 wraps to ~0

        unsigned long long upair = (unsigned long long)(m & hi)
                                 | ((unsigned long long)u1v << 32);
        unsigned long long dpair = (unsigned long long)d1v
                                 | ((unsigned long long)(m & lo) << 32);

        int up = upair ? (w * 32 + __ffsll(upair) - 1 - j)
               : (u2v  ? (w * 32 + 64 + __ffs(u2v) - 1 - j) : 1000);
        int dn = dpair ? (j - (w * 32 - 32 + 63 - __clzll(dpair)))
               : (d2v  ? (j - (w * 32 - 64 + 31 - __clz(d2v))) : 1000);
        int d = min(min(up, dn), 255);              // empty-row sentinel
        g_rd[pair][base + lp] = (unsigned char)d;   // u8 exchange (d <= 95 or 255)
    }

    // ---- per-pair barrier: all 8 bands' rd visible ----
    __syncthreads();
    if (tid == 0) {
        __threadfence();                            // release rd writes
        unsigned arrived = atomicAdd(&g_c1[pair], 1u) + 1u;
        if (arrived < BANDS) {                      // last arriver skips the poll
            volatile unsigned* c = &g_c1[pair];
            while (*c < BANDS) { }
        }
        __threadfence();                            // acquire
    }
    __syncthreads();

    // ---- Phase 3a: pull full 9KB rd tile L2 -> smem, 64-bit loads ----
    {
        const uint2* gsrc = (const uint2*)&g_rd[pair][0];   // 1152 uint2
        uint2* sdst = (uint2*)s_rd;
        #pragma unroll
        for (int k = 0; k < 3; k++)
            sdst[tid + k * NT] = __ldcg(gsrc + tid + k * NT);
    }
    __syncthreads();

    // ---- Phase 3b: exact early-exit ring search (columns), branch-free body ----
    int maxd2 = -1;
    #pragma unroll
    for (int k = 0; k < PPT; k++) {
        const int lp = tid + k * NT;
        if ((s_srcbits[lp >> 5] >> (lp & 31)) & 1u) {
            const int p = base + lp;
            int d0 = (int)s_rd[p];
            int best = d0 * d0;                     // sentinel 255^2 > any true d2
            for (int r = 1; r < GH && r * r < best; r++) {
                int rr = r * r;
                int du = (int)s_rd[p - r * GW];     // pad rows make this always safe
                int dd = (int)s_rd[p + r * GW];
                best = min(best, min(rr + du * du, rr + dd * dd));
            }
            maxd2 = max(maxd2, best);
        }
    }

    // ---- Phase 4: REDUX warp max -> block max -> atomicMax -> flat completion ----
    maxd2 = __reduce_max_sync(0xffffffffu, maxd2);
    if ((tid & 31) == 0) s_warpmax[tid >> 5] = maxd2;
    __syncthreads();

    if (tid == 0) {
        int m = -1;
        #pragma unroll
        for (int w = 0; w < NT / 32; w++) m = max(m, s_warpmax[w]);
        if (m >= 0) atomicMax(&g_pairmax[pair], m);

        __threadfence();                            // release max/tcnt writes
        unsigned done = atomicAdd(&g_c2, 1u);
        if (done == NBLK - 1) {                     // last block finalizes
            __threadfence();                        // acquire all blocks' writes
            // vectorized batched L2 loads: 8 x LDG.128 instead of 32 scalars
            int4 pmv[4], tcv[4];
            #pragma unroll
            for (int q = 0; q < 4; q++) {
                pmv[q] = __ldcg(((const int4*)g_pairmax) + q);
                tcv[q] = __ldcg(((const int4*)g_tcnt) + q);
            }
            const int* pm = (const int*)pmv;
            const int* tc = (const int*)tcv;
            float s = 0.0f;
            #pragma unroll
            for (int q = 0; q < 8; q++) {
                float v0 = (pm[2*q]   < 0) ? 0.0f : ((tc[2*q]   == 0) ? 1e9f : sqrtf((float)pm[2*q])   * (1.0f/96.0f));
                float v1 = (pm[2*q+1] < 0) ? 0.0f : ((tc[2*q+1] == 0) ? 1e9f : sqrtf((float)pm[2*q+1]) * (1.0f/96.0f));
                s += fmaxf(v0, v1);
            }
            out[0] = s * 0.125f;
            // reset all control state for the next graph replay
            #pragma unroll
            for (int q = 0; q < NPAIR; q++) {
                g_pairmax[q] = -1;
                g_tcnt[q]    = 0;
                g_c1[q]      = 0;
            }
            g_c2 = 0;
            __threadfence();
        }
    }
}

extern "C" void kernel_launch(void* const* d_in, const int* in_sizes, int n_in,
                              void* d_out, int out_size)
{
    const float* predict = (const float*)d_in[0];
    const float* target  = (const float*)d_in[1];
    hausdorff_kernel<<<NBLK, NT>>>(predict, target, (float*)d_out);
}

// round 17
// speedup vs baseline: 1.2446x; 1.0245x over previous
#include <cuda_runtime.h>
#include <math.h>

#define HWSZ   9216
#define GH     96
#define GW     96
#define NPAIR  16                  // 8 samples x 2 directions
#define BANDS  8
#define RPB    (GH / BANDS)        // 12 rows per band
#define BPX    (RPB * GW)          // 1152 pixels per band
#define NT     384
#define PPT    (BPX / NT)          // 3 pixels per thread, exact
#define NBLK   (NPAIR * BANDS)     // 128 blocks
#define PADR   GH                  // sentinel rows above/below the rd tile

// global scratch (per-pair 1D row distance, u8) + control state
__device__ unsigned char g_rd[NPAIR][HWSZ];
__device__ int      g_pairmax[NPAIR] = {-1,-1,-1,-1,-1,-1,-1,-1,
                                        -1,-1,-1,-1,-1,-1,-1,-1};
__device__ int      g_tcnt[NPAIR];        // zero-init
__device__ unsigned g_c1[NPAIR];          // per-pair band barrier, zero-init
__device__ unsigned g_c2 = 0;             // completion counter (REDG arrivals, no return)

// pair = 2*sample + dir.
//   dir 0: src = A & ~B, tgt = B   (distA)
//   dir 1: src = ~A & B, tgt = A   (distB)
__global__ __launch_bounds__(NT) void hausdorff_kernel(
    const float* __restrict__ predict,
    const float* __restrict__ target,
    float* __restrict__ out)
{
    const int pair = blockIdx.x >> 3;
    const int band = blockIdx.x & 7;
    const int dir  = pair & 1;
    const int tid  = threadIdx.x;
    const int base = band * BPX;           // absolute pixel base of this band

    // padded row-bit layout: 8 words/row = [0,0, w0,w1,w2, 0,0,0]; row base = i*8+2
    __shared__ unsigned       s_tgtpad[RPB * 8];    // 96 words
    __shared__ unsigned       s_srcbits[BPX / 32];  // 36 words
    // rd tile padded with PADR sentinel rows above and below: ring loop is branch-free
    __shared__ unsigned char  s_rdbuf[(GH + 2 * PADR) * GW];   // 27648 B
    __shared__ int            s_warpmax[NT / 32];
    __shared__ int            s_wcnt[NT / 32];

    unsigned char* const s_rd = s_rdbuf + PADR * GW;  // s_rd[0..HWSZ) = real tile

    const float* pa = predict + (pair >> 1) * HWSZ;
    const float* pb = target  + (pair >> 1) * HWSZ;

    // ---- prefetch input scalars first: start the LDG wave before any setup ----
    float va[PPT], vb[PPT];
    #pragma unroll
    for (int k = 0; k < PPT; k++) {
        const int p = base + tid + k * NT;
        va[k] = pa[p];
        vb[k] = pb[p];
    }

    // fill sentinel pad rows (255 => d2 contribution >= rr + 65025, never the min)
    {
        uint4 s255 = make_uint4(0xffffffffu, 0xffffffffu, 0xffffffffu, 0xffffffffu);
        uint4* lo = (uint4*)s_rdbuf;                        // PADR*GW/16 = 576 uint4
        uint4* hi = (uint4*)(s_rdbuf + (PADR + GH) * GW);
        #pragma unroll
        for (int k = 0; k < (PADR * GW / 16) / NT + 1; k++) {
            const int q = tid + k * NT;
            if (q < PADR * GW / 16) { lo[q] = s255; hi[q] = s255; }
        }
    }

    // zero the 5 pad words per row (disjoint from ballot-written data words)
    if (tid < RPB * 5) {
        int r = tid / 5, pi = tid % 5;
        s_tgtpad[r * 8 + ((pi < 2) ? pi : pi + 3)] = 0u;
    }

    // ---- Phase 1: masks for this band (rintf(x)>0.5 <=> x>0.5, half-even) ----
    int tcount = 0;
    #pragma unroll
    for (int k = 0; k < PPT; k++) {
        const int lp = tid + k * NT;       // 0..1151, lane0 word-aligned
        bool a = va[k] > 0.5f;
        bool b = vb[k] > 0.5f;
        bool t = dir ? a : b;
        bool s = dir ? ((!a) && b) : (a && (!b));
        unsigned tb = __ballot_sync(0xffffffffu, t);
        unsigned sb = __ballot_sync(0xffffffffu, s);
        if ((tid & 31) == 0) {
            const int ww = lp >> 5;        // 0..35
            const int li = ww / 3, wi = ww - li * 3;
            s_tgtpad[li * 8 + 2 + wi] = tb;
            s_srcbits[ww] = sb;
            tcount += __popc(tb);
        }
    }
    if ((tid & 31) == 0) s_wcnt[tid >> 5] = tcount;   // smem, not global atomics
    __syncthreads();

    // single global atomic per block for the tgt count (overlaps phase 2 in other warps)
    if (tid == 0) {
        int tc = 0;
        #pragma unroll
        for (int w = 0; w < NT / 32; w++) tc += s_wcnt[w];
        if (tc) atomicAdd(&g_tcnt[pair], tc);
    }

    // ---- Phase 2: 1D row distance via padded-row indexed loads + 64-bit scans ----
    #pragma unroll
    for (int k = 0; k < PPT; k++) {
        const int lp = tid + k * NT;
        const int li = lp / GW;
        const int j  = lp - li * GW;
        const int w  = j >> 5, off = j & 31;
        const unsigned* bw = s_tgtpad + li * 8 + 2 + w;   // padded: bw[-2..2] valid
        unsigned d2v = bw[-2], d1v = bw[-1], m = bw[0], u1v = bw[1], u2v = bw[2];
        unsigned hi = 0xffffffffu << off;
        unsigned lo = (2u << off) - 1u;     // off=31 wraps to ~0

        unsigned long long upair = (unsigned long long)(m & hi)
                                 | ((unsigned long long)u1v << 32);
        unsigned long long dpair = (unsigned long long)d1v
                                 | ((unsigned long long)(m & lo) << 32);

        int up = upair ? (w * 32 + __ffsll(upair) - 1 - j)
               : (u2v  ? (w * 32 + 64 + __ffs(u2v) - 1 - j) : 1000);
        int dn = dpair ? (j - (w * 32 - 32 + 63 - __clzll(dpair)))
               : (d2v  ? (j - (w * 32 - 64 + 31 - __clz(d2v))) : 1000);
        int d = min(min(up, dn), 255);              // empty-row sentinel
        g_rd[pair][base + lp] = (unsigned char)d;   // u8 exchange (d <= 95 or 255)
    }

    // ---- per-pair barrier: all 8 bands' rd visible ----
    __syncthreads();
    if (tid == 0) {
        __threadfence();                            // release rd writes
        unsigned arrived = atomicAdd(&g_c1[pair], 1u) + 1u;
        if (arrived < BANDS) {                      // last arriver skips the poll
            volatile unsigned* c = &g_c1[pair];
            while (*c < BANDS) { }
        }
        __threadfence();                            // acquire
    }
    __syncthreads();

    // ---- Phase 3a: pull full 9KB rd tile L2 -> smem, 64-bit loads ----
    {
        const uint2* gsrc = (const uint2*)&g_rd[pair][0];   // 1152 uint2
        uint2* sdst = (uint2*)s_rd;
        #pragma unroll
        for (int k = 0; k < 3; k++)
            sdst[tid + k * NT] = __ldcg(gsrc + tid + k * NT);
    }
    __syncthreads();

    // ---- Phase 3b: exact early-exit ring search (columns), branch-free body ----
    int maxd2 = -1;
    #pragma unroll
    for (int k = 0; k < PPT; k++) {
        const int lp = tid + k * NT;
        if ((s_srcbits[lp >> 5] >> (lp & 31)) & 1u) {
            const int p = base + lp;
            int d0 = (int)s_rd[p];
            int best = d0 * d0;                     // sentinel 255^2 > any true d2
            for (int r = 1; r < GH && r * r < best; r++) {
                int rr = r * r;
                int du = (int)s_rd[p - r * GW];     // pad rows make this always safe
                int dd = (int)s_rd[p + r * GW];
                best = min(best, min(rr + du * du, rr + dd * dd));
            }
            maxd2 = max(maxd2, best);
        }
    }

    // ---- Phase 4: REDUX warp max -> block max -> atomicMax -> REDG completion ----
    maxd2 = __reduce_max_sync(0xffffffffu, maxd2);
    if ((tid & 31) == 0) s_warpmax[tid >> 5] = maxd2;
    __syncthreads();

    if (tid == 0) {
        int m = -1;
        #pragma unroll
        for (int w = 0; w < NT / 32; w++) m = max(m, s_warpmax[w]);
        if (m >= 0) atomicMax(&g_pairmax[pair], m);

        __threadfence();                            // release max/tcnt writes
        // pipelined no-return arrival: REDG, not a serialized return-atomic
        asm volatile("red.global.add.u32 [%0], 1;" :: "l"(&g_c2) : "memory");
    }

    // ---- dedicated finalizer: block 0 polls the counter, then reduces ----
    if (blockIdx.x == 0 && tid == 0) {
        volatile unsigned* c = &g_c2;
        while (*c < NBLK) { }                       // overlaps others' arrivals
        __threadfence();                            // acquire all blocks' writes
        // vectorized batched L2 loads: 8 x LDG.128 instead of 32 scalars
        int4 pmv[4], tcv[4];
        #pragma unroll
        for (int q = 0; q < 4; q++) {
            pmv[q] = __ldcg(((const int4*)g_pairmax) + q);
            tcv[q] = __ldcg(((const int4*)g_tcnt) + q);
        }
        const int* pm = (const int*)pmv;
        const int* tc = (const int*)tcv;
        float s = 0.0f;
        #pragma unroll
        for (int q = 0; q < 8; q++) {
            float v0 = (pm[2*q]   < 0) ? 0.0f : ((tc[2*q]   == 0) ? 1e9f : sqrtf((float)pm[2*q])   * (1.0f/96.0f));
            float v1 = (pm[2*q+1] < 0) ? 0.0f : ((tc[2*q+1] == 0) ? 1e9f : sqrtf((float)pm[2*q+1]) * (1.0f/96.0f));
            s += fmaxf(v0, v1);
        }
        out[0] = s * 0.125f;
        // reset all control state for the next graph replay (all blocks have arrived)
        #pragma unroll
        for (int q = 0; q < NPAIR; q++) {
            g_pairmax[q] = -1;
            g_tcnt[q]    = 0;
            g_c1[q]      = 0;
        }
        g_c2 = 0;
        __threadfence();
    }
}

extern "C" void kernel_launch(void* const* d_in, const int* in_sizes, int n_in,
                              void* d_out, int out_size)
{
    const float* predict = (const float*)d_in[0];
    const float* target  = (const float*)d_in[1];
    hausdorff_kernel<<<NBLK, NT>>>(predict, target, (float*)d_out);
}